// round 1
// baseline (speedup 1.0000x reference)
#include <cuda_runtime.h>
#include <math.h>
#include <stdint.h>

#define B_TOK 2048
#define E_EXP 16
#define TOPK  4
#define D_IN  1536
#define H_DIM 1024
#define NHEAD 204
#define NHEAD_PAD 256
#define CAP   2048
#define EPS_F 2.220446049250313e-16f

// ---------------- scratch (__device__ globals; no allocations) ----------------
__device__ float g_x[B_TOK * D_IN];                          // 12.6 MB
__device__ int   g_cnt[E_EXP];
__device__ int   g_rows[E_EXP * CAP];
__device__ float g_gate[B_TOK * TOPK];
__device__ int   g_slot[B_TOK * TOPK];
__device__ float g_h1[(size_t)E_EXP * CAP * H_DIM];          // 134 MB
__device__ float g_h2[(size_t)E_EXP * CAP * H_DIM];          // 134 MB
__device__ float g_hl[(size_t)E_EXP * CAP * NHEAD_PAD];      // 33.5 MB
__device__ float g_wh[(size_t)E_EXP * H_DIM * NHEAD_PAD];    // 16.8 MB
__device__ float g_bh[E_EXP * NHEAD_PAD];

// ---------------- init ----------------
__global__ void init_kernel() {
    if (threadIdx.x < E_EXP) g_cnt[threadIdx.x] = 0;
}

// ---------------- pack head weights [E,H,36|36|132] -> [E,H,256] ----------------
__global__ void pack_heads(const float* __restrict__ Ws, const float* __restrict__ bs,
                           const float* __restrict__ Wo, const float* __restrict__ bo,
                           const float* __restrict__ Wp, const float* __restrict__ bp) {
    int idx = blockIdx.x * blockDim.x + threadIdx.x;
    int total = E_EXP * H_DIM * NHEAD_PAD;
    if (idx < total) {
        int n  = idx % NHEAD_PAD;
        int eh = idx / NHEAD_PAD;      // e*H + h
        float v = 0.0f;
        if (n < 36)        v = Ws[eh * 36 + n];
        else if (n < 72)   v = Wo[eh * 36 + (n - 36)];
        else if (n < 204)  v = Wp[eh * 132 + (n - 72)];
        g_wh[idx] = v;
    }
    if (idx < E_EXP * NHEAD_PAD) {
        int n = idx % NHEAD_PAD;
        int e = idx / NHEAD_PAD;
        float v = 0.0f;
        if (n < 36)        v = bs[e * 36 + n];
        else if (n < 72)   v = bo[e * 36 + (n - 36)];
        else if (n < 204)  v = bp[e * 132 + (n - 72)];
        g_bh[idx] = v;
    }
}

// ---------------- gating: concat x, logits, top-4, softmax, slot assign ----------------
__global__ void gating_kernel(const float* __restrict__ sf, const float* __restrict__ of,
                              const float* __restrict__ ppf, const float* __restrict__ pvf,
                              const float* __restrict__ wg, const float* __restrict__ wn,
                              const float* __restrict__ noise) {
    int b = blockIdx.x;
    __shared__ float sx[D_IN];
    __shared__ float part[8][32];
    int t = threadIdx.x;

    for (int i = t; i < D_IN; i += 256) {
        float v;
        if (i < 512)        v = sf[b * 512 + i];
        else if (i < 1024)  v = of[b * 512 + (i - 512)];
        else if (i < 1280)  v = ppf[b * 256 + (i - 1024)];
        else                v = pvf[b * 256 + (i - 1280)];
        sx[i] = v;
        g_x[b * D_IN + i] = v;
    }
    __syncthreads();

    int w = t >> 5, lane = t & 31;
    int e = lane & 15;
    const float* wm = (lane < 16) ? wg : wn;
    int d0 = w * 192;
    float a0 = 0.f, a1 = 0.f, a2 = 0.f, a3 = 0.f;
    #pragma unroll 4
    for (int d = d0; d < d0 + 192; d += 4) {
        a0 += sx[d + 0] * wm[(d + 0) * 16 + e];
        a1 += sx[d + 1] * wm[(d + 1) * 16 + e];
        a2 += sx[d + 2] * wm[(d + 2) * 16 + e];
        a3 += sx[d + 3] * wm[(d + 3) * 16 + e];
    }
    part[w][lane] = (a0 + a1) + (a2 + a3);
    __syncthreads();

    if (t < 32) {
        float s = 0.f;
        #pragma unroll
        for (int w2 = 0; w2 < 8; w2++) s += part[w2][t];
        part[0][t] = s;   // t<16: clean logit; t>=16: pre-softplus noise
    }
    __syncthreads();

    if (t == 0) {
        float logits[16];
        #pragma unroll
        for (int i = 0; i < 16; i++) {
            float cl = part[0][i];
            float z  = part[0][16 + i];
            float sp = (z > 20.f) ? z : log1pf(expf(z));
            logits[i] = cl + noise[b * 16 + i] * (sp + 1e-2f);
        }
        int   idx[TOPK];
        float val[TOPK];
        unsigned used = 0u;
        for (int k = 0; k < TOPK; k++) {
            float best = -INFINITY; int bi = 0;
            for (int i = 0; i < 16; i++) {
                if (!((used >> i) & 1u) && logits[i] > best) { best = logits[i]; bi = i; }
            }
            used |= (1u << bi); idx[k] = bi; val[k] = best;
        }
        float m = val[0];
        float g[TOPK], s = 0.f;
        #pragma unroll
        for (int k = 0; k < TOPK; k++) { g[k] = expf(val[k] - m); s += g[k]; }
        #pragma unroll
        for (int k = 0; k < TOPK; k++) {
            float gate = g[k] / s;
            int ex = idx[k];
            int rank = atomicAdd(&g_cnt[ex], 1);
            int slot = ex * CAP + rank;
            g_rows[slot]       = b;
            g_slot[b * 4 + k]  = slot;
            g_gate[b * 4 + k]  = gate;
        }
    }
}

// ---------------- grouped SGEMM: C[e] = relu?(A[e] @ W[e] + bias[e]) ----------------
// 128x128x8 tile, 256 threads, 8x8 per thread, double-buffered smem.
template<bool GATHER, bool RELU>
__global__ void __launch_bounds__(256, 2)
gemm_expert(const float* __restrict__ Abase, const float* __restrict__ Wbase,
            const float* __restrict__ biasbase, float* __restrict__ Cbase,
            int K, int N) {
    int e  = blockIdx.z;
    int M  = g_cnt[e];
    int m0 = blockIdx.y * 128;
    if (m0 >= M) return;
    int n0 = blockIdx.x * 128;

    const float* Bp   = Wbase + (size_t)e * K * N + n0;
    const float* bias = biasbase + e * N + n0;
    float*       C    = Cbase + ((size_t)e * CAP + m0) * N + n0;

    __shared__ float As[2][8][128];
    __shared__ float Bs[2][8][128];

    int tid = threadIdx.x;
    int am = tid >> 1;
    int ak = (tid & 1) * 4;
    int bk = tid >> 5;
    int bn = (tid & 31) * 4;

    int row;
    if (GATHER) {
        int mg = m0 + am;
        row = g_rows[e * CAP + (mg < M ? mg : (M - 1))];
    } else {
        row = e * CAP + m0 + am;
    }
    const float* aptr = Abase + (size_t)row * K + ak;
    const float* bptr = Bp + (size_t)bk * N + bn;

    int tm = tid >> 4, tn = tid & 15;

    float acc[8][8];
    #pragma unroll
    for (int i = 0; i < 8; i++)
        #pragma unroll
        for (int j = 0; j < 8; j++) acc[i][j] = 0.f;

    int ktiles = K >> 3;

    float4 a_reg = *(const float4*)aptr;
    float4 b_reg = *(const float4*)bptr;
    As[0][ak + 0][am] = a_reg.x;
    As[0][ak + 1][am] = a_reg.y;
    As[0][ak + 2][am] = a_reg.z;
    As[0][ak + 3][am] = a_reg.w;
    *(float4*)&Bs[0][bk][bn] = b_reg;
    __syncthreads();

    for (int kt = 0; kt < ktiles; kt++) {
        int cur = kt & 1;
        if (kt + 1 < ktiles) {
            a_reg = *(const float4*)(aptr + (size_t)(kt + 1) * 8);
            b_reg = *(const float4*)(bptr + (size_t)(kt + 1) * 8 * N);
        }
        #pragma unroll
        for (int k = 0; k < 8; k++) {
            float4 a0 = *(const float4*)&As[cur][k][tm * 4];
            float4 a1 = *(const float4*)&As[cur][k][64 + tm * 4];
            float4 b0 = *(const float4*)&Bs[cur][k][tn * 4];
            float4 b1 = *(const float4*)&Bs[cur][k][64 + tn * 4];
            float av[8] = {a0.x, a0.y, a0.z, a0.w, a1.x, a1.y, a1.z, a1.w};
            float bv[8] = {b0.x, b0.y, b0.z, b0.w, b1.x, b1.y, b1.z, b1.w};
            #pragma unroll
            for (int i = 0; i < 8; i++)
                #pragma unroll
                for (int j = 0; j < 8; j++)
                    acc[i][j] += av[i] * bv[j];
        }
        if (kt + 1 < ktiles) {
            int nxt = cur ^ 1;
            As[nxt][ak + 0][am] = a_reg.x;
            As[nxt][ak + 1][am] = a_reg.y;
            As[nxt][ak + 2][am] = a_reg.z;
            As[nxt][ak + 3][am] = a_reg.w;
            *(float4*)&Bs[nxt][bk][bn] = b_reg;
        }
        __syncthreads();
    }

    #pragma unroll
    for (int i = 0; i < 8; i++) {
        int mi = (i < 4) ? (tm * 4 + i) : (64 + tm * 4 + (i - 4));
        if (m0 + mi < M) {
            #pragma unroll
            for (int jg = 0; jg < 2; jg++) {
                int nb = jg * 64 + tn * 4;
                float4 o;
                o.x = acc[i][jg * 4 + 0] + bias[nb + 0];
                o.y = acc[i][jg * 4 + 1] + bias[nb + 1];
                o.z = acc[i][jg * 4 + 2] + bias[nb + 2];
                o.w = acc[i][jg * 4 + 3] + bias[nb + 3];
                if (RELU) {
                    o.x = fmaxf(o.x, 0.f); o.y = fmaxf(o.y, 0.f);
                    o.z = fmaxf(o.z, 0.f); o.w = fmaxf(o.w, 0.f);
                }
                *(float4*)&C[(size_t)mi * N + nb] = o;
            }
        }
    }
}

// ---------------- combine: fused softmax over 3 head groups + weighted log-sum ----------------
__global__ void combine_kernel(float* __restrict__ out) {
    int b = blockIdx.x;
    __shared__ float vals[TOPK][NHEAD];
    __shared__ float mx[TOPK][3], inv[TOPK][3];
    __shared__ int   slots[TOPK];
    __shared__ float gts[TOPK];
    int t = threadIdx.x;

    if (t < TOPK) { slots[t] = g_slot[b * 4 + t]; gts[t] = g_gate[b * 4 + t]; }
    __syncthreads();

    for (int i = t; i < TOPK * NHEAD; i += 256) {
        int k = i / NHEAD, c = i % NHEAD;
        vals[k][c] = g_hl[(size_t)slots[k] * NHEAD_PAD + c];
    }
    __syncthreads();

    if (t < TOPK * 3) {
        int k = t / 3, grp = t % 3;
        int c0 = (grp == 0) ? 0 : (grp == 1 ? 36 : 72);
        int c1 = (grp == 0) ? 36 : (grp == 1 ? 72 : 204);
        float m = -INFINITY;
        for (int c = c0; c < c1; c++) m = fmaxf(m, vals[k][c]);
        float s = 0.f;
        for (int c = c0; c < c1; c++) s += expf(vals[k][c] - m);
        mx[k][grp]  = m;
        inv[k][grp] = 1.f / s;
    }
    __syncthreads();

    if (t < NHEAD) {
        int grp = (t < 36) ? 0 : ((t < 72) ? 1 : 2);
        float s = 0.f;
        #pragma unroll
        for (int k = 0; k < TOPK; k++)
            s += gts[k] * expf(vals[k][t] - mx[k][grp]) * inv[k][grp];
        float r = logf((s == 0.f) ? EPS_F : s);
        if (t < 36)       out[b * 36 + t] = r;
        else if (t < 72)  out[B_TOK * 36 + b * 36 + (t - 36)] = r;
        else              out[B_TOK * 72 + b * 132 + (t - 72)] = r;
    }
}

// ---------------- launch ----------------
extern "C" void kernel_launch(void* const* d_in, const int* in_sizes, int n_in,
                              void* d_out, int out_size) {
    const float* sf  = (const float*)d_in[0];
    const float* of  = (const float*)d_in[1];
    const float* ppf = (const float*)d_in[2];
    const float* pvf = (const float*)d_in[3];
    const float* wg  = (const float*)d_in[4];
    const float* wn  = (const float*)d_in[5];
    const float* W1  = (const float*)d_in[6];
    const float* b1  = (const float*)d_in[7];
    const float* W2  = (const float*)d_in[8];
    const float* b2  = (const float*)d_in[9];
    const float* Ws  = (const float*)d_in[10];
    const float* bs  = (const float*)d_in[11];
    const float* Wo  = (const float*)d_in[12];
    const float* bo  = (const float*)d_in[13];
    const float* Wp  = (const float*)d_in[14];
    const float* bp  = (const float*)d_in[15];
    const float* noise = (const float*)d_in[16];
    float* out = (float*)d_out;

    // device addresses of scratch symbols (host API, not a stream op: capture-safe)
    static float* p_x   = nullptr;
    static float* p_h1  = nullptr;
    static float* p_h2  = nullptr;
    static float* p_hl  = nullptr;
    static float* p_wh  = nullptr;
    static float* p_bh  = nullptr;
    if (!p_x) {
        cudaGetSymbolAddress((void**)&p_x,  g_x);
        cudaGetSymbolAddress((void**)&p_h1, g_h1);
        cudaGetSymbolAddress((void**)&p_h2, g_h2);
        cudaGetSymbolAddress((void**)&p_hl, g_hl);
        cudaGetSymbolAddress((void**)&p_wh, g_wh);
        cudaGetSymbolAddress((void**)&p_bh, g_bh);
    }

    init_kernel<<<1, 32>>>();
    pack_heads<<<(E_EXP * H_DIM * NHEAD_PAD + 255) / 256, 256>>>(Ws, bs, Wo, bo, Wp, bp);
    gating_kernel<<<B_TOK, 256>>>(sf, of, ppf, pvf, wg, wn, noise);

    // Layer 1: [cnt_e,1536] @ [1536,1024] + b1, relu  (gathered A from g_x)
    gemm_expert<true, true><<<dim3(H_DIM / 128, CAP / 128, E_EXP), 256>>>(
        p_x, W1, b1, p_h1, D_IN, H_DIM);
    // Layer 2: [cnt_e,1024] @ [1024,1024] + b2, relu
    gemm_expert<false, true><<<dim3(H_DIM / 128, CAP / 128, E_EXP), 256>>>(
        p_h1, W2, b2, p_h2, H_DIM, H_DIM);
    // Heads: [cnt_e,1024] @ [1024,256(packed)] + bh
    gemm_expert<false, false><<<dim3(NHEAD_PAD / 128, CAP / 128, E_EXP), 256>>>(
        p_h2, p_wh, p_bh, p_hl, H_DIM, NHEAD_PAD);

    combine_kernel<<<B_TOK, 256>>>(out);
}

// round 3
// speedup vs baseline: 2.1402x; 2.1402x over previous
#include <cuda_runtime.h>
#include <math.h>
#include <stdint.h>

#define B_TOK 2048
#define E_EXP 16
#define TOPK  4
#define D_IN  1536
#define H_DIM 1024
#define NHEAD 204
#define NHEAD_PAD 256
#define CAP   2048
#define EPS_F 2.220446049250313e-16f

// GEMM tiling
#define BM 128
#define BN 128
#define BK 16
#define AK_PAD 24            // A_s row stride in floats (96B, 16B-aligned, conflict-free)
#define BN_PAD 140           // B_s row stride in floats (560B, 16B-aligned, conflict-free)
#define A_STAGE_BYTES (BM * AK_PAD * 4)          // 12288
#define B_STAGE_BYTES (BK * BN_PAD * 4)          // 8960
#define STAGE_BYTES   (A_STAGE_BYTES + B_STAGE_BYTES)  // 21248
#define NSTAGE 4
#define SMEM_GEMM (NSTAGE * STAGE_BYTES)         // 84992

// ---------------- scratch ----------------
__device__ float g_xg[(size_t)E_EXP * CAP * D_IN];
__device__ int   g_cnt[E_EXP];
__device__ float g_gate[B_TOK * TOPK];
__device__ int   g_slot[B_TOK * TOPK];
__device__ float g_h1[(size_t)E_EXP * CAP * H_DIM];
__device__ float g_h2[(size_t)E_EXP * CAP * H_DIM];
__device__ float g_hl[(size_t)E_EXP * CAP * NHEAD_PAD];
__device__ float g_wh[(size_t)E_EXP * H_DIM * NHEAD_PAD];   // [E][K=1024][N=256]
__device__ float g_bh[E_EXP * NHEAD_PAD];

// ---------------- helpers ----------------
__device__ __forceinline__ uint32_t smem_u32(const void* p) {
    uint32_t a;
    asm("{ .reg .u64 t; cvta.to.shared.u64 t, %1; cvt.u32.u64 %0, t; }" : "=r"(a) : "l"(p));
    return a;
}
__device__ __forceinline__ float tf32r(float x) {
    uint32_t u;
    asm("cvt.rna.tf32.f32 %0, %1;" : "=r"(u) : "f"(x));
    return __uint_as_float(u);
}
__device__ __forceinline__ uint32_t tf32u(float x) {
    uint32_t u;
    asm("cvt.rna.tf32.f32 %0, %1;" : "=r"(u) : "f"(x));
    return u;
}
__device__ __forceinline__ void cp16(uint32_t dst, const void* src) {
    asm volatile("cp.async.cg.shared.global [%0], [%1], 16;" :: "r"(dst), "l"(src));
}
__device__ __forceinline__ void mma_tf32(float* c, const uint32_t* a, const uint32_t* b) {
    asm volatile("mma.sync.aligned.m16n8k8.row.col.f32.tf32.tf32.f32 "
        "{%0,%1,%2,%3}, {%4,%5,%6,%7}, {%8,%9}, {%0,%1,%2,%3};"
        : "+f"(c[0]), "+f"(c[1]), "+f"(c[2]), "+f"(c[3])
        : "r"(a[0]), "r"(a[1]), "r"(a[2]), "r"(a[3]), "r"(b[0]), "r"(b[1]));
}

// ---------------- init ----------------
__global__ void init_kernel() {
    if (threadIdx.x < E_EXP) g_cnt[threadIdx.x] = 0;
}

// ---------------- pack head weights [E,H,36|36|132] -> [E][1024][256] (n-contig), tf32 ----------------
__global__ void pack_heads(const float* __restrict__ Ws, const float* __restrict__ bs,
                           const float* __restrict__ Wo, const float* __restrict__ bo,
                           const float* __restrict__ Wp, const float* __restrict__ bp) {
    size_t idx = (size_t)blockIdx.x * 256 + threadIdx.x;   // over E*1024*256, n fastest
    int n  = (int)(idx & 255);
    size_t eh = idx >> 8;          // e*1024 + k
    float v = 0.0f;
    if (n < 36)       v = Ws[eh * 36 + n];
    else if (n < 72)  v = Wo[eh * 36 + (n - 36)];
    else if (n < 204) v = Wp[eh * 132 + (n - 72)];
    g_wh[idx] = tf32r(v);
    if (idx < E_EXP * NHEAD_PAD) {
        int nn = (int)(idx & 255), ee = (int)(idx >> 8);
        float b = 0.0f;
        if (nn < 36)       b = bs[ee * 36 + nn];
        else if (nn < 72)  b = bo[ee * 36 + (nn - 36)];
        else if (nn < 204) b = bp[ee * 132 + (nn - 72)];
        g_bh[idx] = b;
    }
}

// ---------------- gating ----------------
__global__ void gating_kernel(const float* __restrict__ sf, const float* __restrict__ of,
                              const float* __restrict__ ppf, const float* __restrict__ pvf,
                              const float* __restrict__ wg, const float* __restrict__ wn,
                              const float* __restrict__ noise) {
    int b = blockIdx.x;
    __shared__ __align__(16) float sx[D_IN];
    __shared__ float part[8][32];
    __shared__ int s_slot[TOPK];
    int t = threadIdx.x;

    for (int i = t; i < D_IN; i += 256) {
        float v;
        if (i < 512)        v = sf[b * 512 + i];
        else if (i < 1024)  v = of[b * 512 + (i - 512)];
        else if (i < 1280)  v = ppf[b * 256 + (i - 1024)];
        else                v = pvf[b * 256 + (i - 1280)];
        sx[i] = v;
    }
    __syncthreads();

    int w = t >> 5, lane = t & 31;
    int e = lane & 15;
    const float* wm = (lane < 16) ? wg : wn;
    int d0 = w * 192;
    float a0 = 0.f, a1 = 0.f, a2 = 0.f, a3 = 0.f;
    #pragma unroll 4
    for (int d = d0; d < d0 + 192; d += 4) {
        a0 += sx[d + 0] * wm[(d + 0) * 16 + e];
        a1 += sx[d + 1] * wm[(d + 1) * 16 + e];
        a2 += sx[d + 2] * wm[(d + 2) * 16 + e];
        a3 += sx[d + 3] * wm[(d + 3) * 16 + e];
    }
    part[w][lane] = (a0 + a1) + (a2 + a3);
    __syncthreads();

    if (t < 32) {
        float s = 0.f;
        #pragma unroll
        for (int w2 = 0; w2 < 8; w2++) s += part[w2][t];
        part[0][t] = s;
    }
    __syncthreads();

    if (t == 0) {
        float logits[16];
        #pragma unroll
        for (int i = 0; i < 16; i++) {
            float cl = part[0][i];
            float z  = part[0][16 + i];
            float sp = (z > 20.f) ? z : log1pf(expf(z));
            logits[i] = cl + noise[b * 16 + i] * (sp + 1e-2f);
        }
        int   idx[TOPK];
        float val[TOPK];
        unsigned used = 0u;
        for (int k = 0; k < TOPK; k++) {
            float best = -INFINITY; int bi = 0;
            for (int i = 0; i < 16; i++)
                if (!((used >> i) & 1u) && logits[i] > best) { best = logits[i]; bi = i; }
            used |= (1u << bi); idx[k] = bi; val[k] = best;
        }
        float m = val[0];
        float g[TOPK], s = 0.f;
        #pragma unroll
        for (int k = 0; k < TOPK; k++) { g[k] = expf(val[k] - m); s += g[k]; }
        #pragma unroll
        for (int k = 0; k < TOPK; k++) {
            int ex = idx[k];
            int rank = atomicAdd(&g_cnt[ex], 1);
            int slot = ex * CAP + rank;
            s_slot[k]          = slot;
            g_slot[b * 4 + k]  = slot;
            g_gate[b * 4 + k]  = g[k] / s;
        }
    }
    __syncthreads();

    #pragma unroll
    for (int k = 0; k < TOPK; k++) {
        float4* dst = (float4*)(g_xg + (size_t)s_slot[k] * D_IN);
        const float4* src = (const float4*)sx;
        for (int i = t; i < D_IN / 4; i += 256) {
            float4 v = src[i];
            v.x = tf32r(v.x); v.y = tf32r(v.y); v.z = tf32r(v.z); v.w = tf32r(v.w);
            dst[i] = v;
        }
    }
}

// ---------------- tf32 mma.sync grouped GEMM ----------------
// A: [E*CAP][Ktot] row-major (tf32-rounded). B: [E][Ktot][Ntot] row-major (weights).
// C[e] = act(A[e] @ B[e] + bias[e]).  k-permuted fragments: mma col c = smem col 2c, c+4 = 2c+1.
template<bool RELU, bool CVT>
__global__ void __launch_bounds__(256, 2)
gemm_mma(const float* __restrict__ A, const float* __restrict__ B,
         const float* __restrict__ bias, float* __restrict__ C,
         int Ktot, int Ntot) {
    extern __shared__ char smem[];
    const int e  = blockIdx.z;
    const int M  = g_cnt[e];
    const int m0 = blockIdx.y * BM;
    if (m0 >= M) return;
    const int n0 = blockIdx.x * BN;

    const uint32_t sbase = smem_u32(smem);
    const int tid = threadIdx.x;
    const int wid = tid >> 5, lane = tid & 31;
    const int wm = wid >> 2;          // 0..1  (64-row slab)
    const int wn = wid & 3;           // 0..3  (32-col slab)
    const int r  = lane >> 2;         // 0..7
    const int c  = lane & 3;          // 0..3

    const float* Abase = A + (size_t)(e * CAP + m0) * Ktot;
    const float* Bbase = B + (size_t)e * Ktot * Ntot + n0;
    const int KT = Ktot / BK;

    // gmem load indices (4 chunks of 16B per thread per stage)
    const int a_row = tid >> 1;              // 0..127
    const int a_ch  = (tid & 1) * 2;         // chunk pairs: this thread does ch, ch+1
    const int b_row = tid >> 4;              // 0..15
    const int b_ch  = (tid & 15) * 2;        // 0..30

    auto load_stage = [&](int kt) {
        uint32_t sa = sbase + (kt & 3) * STAGE_BYTES;
        uint32_t sb = sa + A_STAGE_BYTES;
        const float* ga = Abase + kt * BK;
        const float* gb = Bbase + (size_t)(kt * BK) * Ntot;
        // A: 128 rows x 16 floats
        cp16(sa + a_row * (AK_PAD * 4) + a_ch * 16,       ga + (size_t)a_row * Ktot + a_ch * 4);
        cp16(sa + a_row * (AK_PAD * 4) + (a_ch + 1) * 16, ga + (size_t)a_row * Ktot + (a_ch + 1) * 4);
        // B: 16 rows x 128 floats
        cp16(sb + b_row * (BN_PAD * 4) + b_ch * 16,       gb + (size_t)b_row * Ntot + b_ch * 4);
        cp16(sb + b_row * (BN_PAD * 4) + (b_ch + 1) * 16, gb + (size_t)b_row * Ntot + (b_ch + 1) * 4);
        asm volatile("cp.async.commit_group;" ::: "memory");
    };

    load_stage(0);
    if (KT > 1) load_stage(1); else asm volatile("cp.async.commit_group;" ::: "memory");
    if (KT > 2) load_stage(2); else asm volatile("cp.async.commit_group;" ::: "memory");

    float acc[4][4][4];
    #pragma unroll
    for (int i = 0; i < 4; i++)
        #pragma unroll
        for (int j = 0; j < 4; j++)
            #pragma unroll
            for (int k = 0; k < 4; k++) acc[i][j][k] = 0.f;

    // per-warp smem fragment bases
    const uint32_t a_frag_base = sbase + ((wm * 64 + r) * AK_PAD + 2 * c) * 4;
    // B fragment: row (2c) stride BN_PAD, col wn*32 + nt*8 + r
    const uint32_t b_frag_base = sbase + A_STAGE_BYTES + ((2 * c) * BN_PAD + wn * 32 + r) * 4;

    for (int kt = 0; kt < KT; kt++) {
        asm volatile("cp.async.wait_group 2;" ::: "memory");
        __syncthreads();
        if (kt + 3 < KT) load_stage(kt + 3);
        else asm volatile("cp.async.commit_group;" ::: "memory");

        uint32_t sa = a_frag_base + (kt & 3) * STAGE_BYTES;
        uint32_t sb = b_frag_base + (kt & 3) * STAGE_BYTES;
        #pragma unroll
        for (int ks = 0; ks < 2; ks++) {
            uint32_t af[4][4];
            #pragma unroll
            for (int mt = 0; mt < 4; mt++) {
                float2 lo, hi;
                asm volatile("ld.shared.v2.f32 {%0,%1}, [%2];"
                             : "=f"(lo.x), "=f"(lo.y)
                             : "r"(sa + (mt * 16) * (AK_PAD * 4) + ks * 32));
                asm volatile("ld.shared.v2.f32 {%0,%1}, [%2];"
                             : "=f"(hi.x), "=f"(hi.y)
                             : "r"(sa + (mt * 16 + 8) * (AK_PAD * 4) + ks * 32));
                af[mt][0] = __float_as_uint(lo.x);
                af[mt][1] = __float_as_uint(hi.x);
                af[mt][2] = __float_as_uint(lo.y);
                af[mt][3] = __float_as_uint(hi.y);
            }
            uint32_t bf[4][2];
            #pragma unroll
            for (int nt = 0; nt < 4; nt++) {
                float v0, v1;
                asm volatile("ld.shared.f32 %0, [%1];" : "=f"(v0)
                             : "r"(sb + (ks * 8 * BN_PAD + nt * 8) * 4));
                asm volatile("ld.shared.f32 %0, [%1];" : "=f"(v1)
                             : "r"(sb + ((ks * 8 + 1) * BN_PAD + nt * 8) * 4));
                bf[nt][0] = tf32u(v0);
                bf[nt][1] = tf32u(v1);
            }
            #pragma unroll
            for (int mt = 0; mt < 4; mt++)
                #pragma unroll
                for (int nt = 0; nt < 4; nt++)
                    mma_tf32(acc[mt][nt], af[mt], bf[nt]);
        }
        __syncthreads();
    }
    asm volatile("cp.async.wait_group 0;" ::: "memory");

    // epilogue: bias + relu + tf32 round, direct float2 stores
    #pragma unroll
    for (int nt = 0; nt < 4; nt++) {
        int col = n0 + wn * 32 + nt * 8 + 2 * c;
        float bb0 = __ldg(bias + e * Ntot + col);
        float bb1 = __ldg(bias + e * Ntot + col + 1);
        #pragma unroll
        for (int mt = 0; mt < 4; mt++) {
            int row0 = wm * 64 + mt * 16 + r;
            float v0 = acc[mt][nt][0] + bb0;
            float v1 = acc[mt][nt][1] + bb1;
            float v2 = acc[mt][nt][2] + bb0;
            float v3 = acc[mt][nt][3] + bb1;
            if (RELU) {
                v0 = fmaxf(v0, 0.f); v1 = fmaxf(v1, 0.f);
                v2 = fmaxf(v2, 0.f); v3 = fmaxf(v3, 0.f);
            }
            if (CVT) {
                v0 = tf32r(v0); v1 = tf32r(v1);
                v2 = tf32r(v2); v3 = tf32r(v3);
            }
            if (m0 + row0 < M) {
                float2 p = {v0, v1};
                *(float2*)(C + (size_t)(e * CAP + m0 + row0) * Ntot + col) = p;
            }
            if (m0 + row0 + 8 < M) {
                float2 p = {v2, v3};
                *(float2*)(C + (size_t)(e * CAP + m0 + row0 + 8) * Ntot + col) = p;
            }
        }
    }
}

// ---------------- combine ----------------
__global__ void combine_kernel(float* __restrict__ out) {
    int b = blockIdx.x;
    __shared__ float vals[TOPK][NHEAD];
    __shared__ float mx[TOPK][3], inv[TOPK][3];
    __shared__ int   slots[TOPK];
    __shared__ float gts[TOPK];
    int t = threadIdx.x;

    if (t < TOPK) { slots[t] = g_slot[b * 4 + t]; gts[t] = g_gate[b * 4 + t]; }
    __syncthreads();

    for (int i = t; i < TOPK * NHEAD; i += 256) {
        int k = i / NHEAD, cc = i % NHEAD;
        vals[k][cc] = g_hl[(size_t)slots[k] * NHEAD_PAD + cc];
    }
    __syncthreads();

    if (t < TOPK * 3) {
        int k = t / 3, grp = t % 3;
        int c0 = (grp == 0) ? 0 : (grp == 1 ? 36 : 72);
        int c1 = (grp == 0) ? 36 : (grp == 1 ? 72 : 204);
        float m = -INFINITY;
        for (int cc = c0; cc < c1; cc++) m = fmaxf(m, vals[k][cc]);
        float s = 0.f;
        for (int cc = c0; cc < c1; cc++) s += expf(vals[k][cc] - m);
        mx[k][grp]  = m;
        inv[k][grp] = 1.f / s;
    }
    __syncthreads();

    if (t < NHEAD) {
        int grp = (t < 36) ? 0 : ((t < 72) ? 1 : 2);
        float s = 0.f;
        #pragma unroll
        for (int k = 0; k < TOPK; k++)
            s += gts[k] * expf(vals[k][t] - mx[k][grp]) * inv[k][grp];
        float res = logf((s == 0.f) ? EPS_F : s);
        if (t < 36)       out[b * 36 + t] = res;
        else if (t < 72)  out[B_TOK * 36 + b * 36 + (t - 36)] = res;
        else              out[B_TOK * 72 + b * 132 + (t - 72)] = res;
    }
}

// ---------------- launch ----------------
extern "C" void kernel_launch(void* const* d_in, const int* in_sizes, int n_in,
                              void* d_out, int out_size) {
    const float* sf  = (const float*)d_in[0];
    const float* of  = (const float*)d_in[1];
    const float* ppf = (const float*)d_in[2];
    const float* pvf = (const float*)d_in[3];
    const float* wg  = (const float*)d_in[4];
    const float* wn  = (const float*)d_in[5];
    const float* W1  = (const float*)d_in[6];
    const float* b1  = (const float*)d_in[7];
    const float* W2  = (const float*)d_in[8];
    const float* b2  = (const float*)d_in[9];
    const float* Ws  = (const float*)d_in[10];
    const float* bs  = (const float*)d_in[11];
    const float* Wo  = (const float*)d_in[12];
    const float* bo  = (const float*)d_in[13];
    const float* Wp  = (const float*)d_in[14];
    const float* bp  = (const float*)d_in[15];
    const float* noise = (const float*)d_in[16];
    float* out = (float*)d_out;

    static float* p_xg = nullptr;
    static float* p_h1 = nullptr;
    static float* p_h2 = nullptr;
    static float* p_hl = nullptr;
    static float* p_wh = nullptr;
    static float* p_bh = nullptr;
    if (!p_xg) {
        cudaGetSymbolAddress((void**)&p_xg, g_xg);
        cudaGetSymbolAddress((void**)&p_h1, g_h1);
        cudaGetSymbolAddress((void**)&p_h2, g_h2);
        cudaGetSymbolAddress((void**)&p_hl, g_hl);
        cudaGetSymbolAddress((void**)&p_wh, g_wh);
        cudaGetSymbolAddress((void**)&p_bh, g_bh);
        cudaFuncSetAttribute(gemm_mma<true, true>,
                             cudaFuncAttributeMaxDynamicSharedMemorySize, SMEM_GEMM);
        cudaFuncSetAttribute(gemm_mma<false, false>,
                             cudaFuncAttributeMaxDynamicSharedMemorySize, SMEM_GEMM);
    }

    init_kernel<<<1, 32>>>();
    gating_kernel<<<B_TOK, 256>>>(sf, of, ppf, pvf, wg, wn, noise);
    pack_heads<<<(E_EXP * H_DIM * NHEAD_PAD) / 256, 256>>>(Ws, bs, Wo, bo, Wp, bp);

    // L1: [cnt_e,1536] @ W1[e] -> relu -> h1
    gemm_mma<true, true><<<dim3(H_DIM / BN, CAP / BM, E_EXP), 256, SMEM_GEMM>>>(
        p_xg, W1, b1, p_h1, D_IN, H_DIM);
    // L2: [cnt_e,1024] @ W2[e] -> relu -> h2
    gemm_mma<true, true><<<dim3(H_DIM / BN, CAP / BM, E_EXP), 256, SMEM_GEMM>>>(
        p_h1, W2, b2, p_h2, H_DIM, H_DIM);
    // heads: [cnt_e,1024] @ Wh[e] (N=256 packed)
    gemm_mma<false, false><<<dim3(NHEAD_PAD / BN, CAP / BM, E_EXP), 256, SMEM_GEMM>>>(
        p_h2, p_wh, p_bh, p_hl, H_DIM, NHEAD_PAD);

    combine_kernel<<<B_TOK, 256>>>(out);
}

// round 4
// speedup vs baseline: 3.0463x; 1.4234x over previous
#include <cuda_runtime.h>
#include <math.h>
#include <stdint.h>

#define B_TOK 2048
#define E_EXP 16
#define TOPK  4
#define D_IN  1536
#define H_DIM 1024
#define NHEAD 204
#define NHEAD_PAD 256
#define CAP   2048
#define EPS_F 2.220446049250313e-16f

// GEMM tiling (bf16 m16n8k16)
#define BM 128
#define BN 128
#define BK 32                 // bf16 k per stage
#define KPW 16                // BK/2 u32 words per A row per stage
#define A_STRIDE 20           // u32 stride of A_s rows (conflict-free, 16B-aligned)
#define B_STRIDE 136          // u32 stride of B_s rows (conflict-free, 16B-aligned)
#define A_STAGE (BM * A_STRIDE * 4)       // 10240
#define B_STAGE (16 * B_STRIDE * 4)       // 8704
#define STAGE_BYTES (A_STAGE + B_STAGE)   // 18944
#define SMEM_GEMM (4 * STAGE_BYTES)       // 75776

// ---------------- scratch (bf16 activations as packed u32 pairs) ----------------
__device__ __align__(16) uint32_t g_xa[(size_t)E_EXP * CAP * (D_IN / 2)];
__device__ int   g_cnt[E_EXP];
__device__ float g_gate[B_TOK * TOPK];
__device__ int   g_slot[B_TOK * TOPK];
__device__ __align__(16) uint32_t g_h1[(size_t)E_EXP * CAP * (H_DIM / 2)];
__device__ __align__(16) uint32_t g_h2[(size_t)E_EXP * CAP * (H_DIM / 2)];
__device__ __align__(16) float    g_hl[(size_t)E_EXP * CAP * NHEAD_PAD];
__device__ __align__(16) uint32_t g_w1b[(size_t)E_EXP * (D_IN / 2) * H_DIM];
__device__ __align__(16) uint32_t g_w2b[(size_t)E_EXP * (H_DIM / 2) * H_DIM];
__device__ __align__(16) uint32_t g_whb[(size_t)E_EXP * (H_DIM / 2) * NHEAD_PAD];
__device__ float g_bh[E_EXP * NHEAD_PAD];

// ---------------- helpers ----------------
__device__ __forceinline__ uint32_t smem_u32(const void* p) {
    uint32_t a;
    asm("{ .reg .u64 t; cvta.to.shared.u64 t, %1; cvt.u32.u64 %0, t; }" : "=r"(a) : "l"(p));
    return a;
}
__device__ __forceinline__ uint32_t packbf(float lo, float hi) {
    uint32_t w;
    asm("cvt.rn.bf16x2.f32 %0, %1, %2;" : "=r"(w) : "f"(hi), "f"(lo));
    return w;
}
__device__ __forceinline__ void cp16(uint32_t dst, const void* src) {
    asm volatile("cp.async.cg.shared.global [%0], [%1], 16;" :: "r"(dst), "l"(src));
}
__device__ __forceinline__ void mma_bf16(float* c, const uint32_t* a, const uint32_t* b) {
    asm volatile("mma.sync.aligned.m16n8k16.row.col.f32.bf16.bf16.f32 "
        "{%0,%1,%2,%3}, {%4,%5,%6,%7}, {%8,%9}, {%0,%1,%2,%3};"
        : "+f"(c[0]), "+f"(c[1]), "+f"(c[2]), "+f"(c[3])
        : "r"(a[0]), "r"(a[1]), "r"(a[2]), "r"(a[3]), "r"(b[0]), "r"(b[1]));
}

// ---------------- init ----------------
__global__ void init_kernel() {
    if (threadIdx.x < E_EXP) g_cnt[threadIdx.x] = 0;
}

// ---------------- weight convert: f32 [E][K][N] -> bf16x2 packed [E][K/2][N] ----------------
__global__ void conv_w(const float* __restrict__ src, uint32_t* __restrict__ dst,
                       int Khalf, int N) {
    size_t idx = (size_t)blockIdx.x * 256 + threadIdx.x;   // over E*Khalf*N, n fastest
    size_t n   = idx % N;
    size_t kpe = idx / N;
    size_t kp  = kpe % Khalf;
    size_t e   = kpe / Khalf;
    const float* s = src + ((size_t)e * (2 * Khalf) + 2 * kp) * N + n;
    dst[idx] = packbf(s[0], s[N]);
}

// ---------------- pack head weights -> bf16x2 [E][512][256], bias -> f32 [E][256] ----------------
__global__ void pack_heads(const float* __restrict__ Ws, const float* __restrict__ bs,
                           const float* __restrict__ Wo, const float* __restrict__ bo,
                           const float* __restrict__ Wp, const float* __restrict__ bp) {
    size_t idx = (size_t)blockIdx.x * 256 + threadIdx.x;   // over E*512*256
    int n  = (int)(idx & 255);
    int kp = (int)((idx >> 8) & 511);
    int e  = (int)(idx >> 17);
    float lo = 0.f, hi = 0.f;
    size_t base0 = (size_t)e * H_DIM + 2 * kp;
    if (n < 36)       { lo = Ws[base0 * 36 + n];        hi = Ws[(base0 + 1) * 36 + n]; }
    else if (n < 72)  { lo = Wo[base0 * 36 + (n - 36)]; hi = Wo[(base0 + 1) * 36 + (n - 36)]; }
    else if (n < 204) { lo = Wp[base0 * 132 + (n - 72)]; hi = Wp[(base0 + 1) * 132 + (n - 72)]; }
    g_whb[idx] = packbf(lo, hi);
    if (idx < E_EXP * NHEAD_PAD) {
        int nn = (int)(idx & 255), ee = (int)(idx >> 8);
        float b = 0.0f;
        if (nn < 36)       b = bs[ee * 36 + nn];
        else if (nn < 72)  b = bo[ee * 36 + (nn - 36)];
        else if (nn < 204) b = bp[ee * 132 + (nn - 72)];
        g_bh[idx] = b;
    }
}

// ---------------- gating (fp32 exact) + bf16 scatter of x ----------------
__global__ void gating_kernel(const float* __restrict__ sf, const float* __restrict__ of,
                              const float* __restrict__ ppf, const float* __restrict__ pvf,
                              const float* __restrict__ wg, const float* __restrict__ wn,
                              const float* __restrict__ noise) {
    int b = blockIdx.x;
    __shared__ __align__(16) float sx[D_IN];
    __shared__ float part[8][32];
    __shared__ int s_slot[TOPK];
    int t = threadIdx.x;

    for (int i = t; i < D_IN; i += 256) {
        float v;
        if (i < 512)        v = sf[b * 512 + i];
        else if (i < 1024)  v = of[b * 512 + (i - 512)];
        else if (i < 1280)  v = ppf[b * 256 + (i - 1024)];
        else                v = pvf[b * 256 + (i - 1280)];
        sx[i] = v;
    }
    __syncthreads();

    int w = t >> 5, lane = t & 31;
    int e = lane & 15;
    const float* wm = (lane < 16) ? wg : wn;
    int d0 = w * 192;
    float a0 = 0.f, a1 = 0.f, a2 = 0.f, a3 = 0.f;
    #pragma unroll 4
    for (int d = d0; d < d0 + 192; d += 4) {
        a0 += sx[d + 0] * wm[(d + 0) * 16 + e];
        a1 += sx[d + 1] * wm[(d + 1) * 16 + e];
        a2 += sx[d + 2] * wm[(d + 2) * 16 + e];
        a3 += sx[d + 3] * wm[(d + 3) * 16 + e];
    }
    part[w][lane] = (a0 + a1) + (a2 + a3);
    __syncthreads();

    if (t < 32) {
        float s = 0.f;
        #pragma unroll
        for (int w2 = 0; w2 < 8; w2++) s += part[w2][t];
        part[0][t] = s;
    }
    __syncthreads();

    if (t == 0) {
        float logits[16];
        #pragma unroll
        for (int i = 0; i < 16; i++) {
            float cl = part[0][i];
            float z  = part[0][16 + i];
            float sp = (z > 20.f) ? z : log1pf(expf(z));
            logits[i] = cl + noise[b * 16 + i] * (sp + 1e-2f);
        }
        int   idx[TOPK];
        float val[TOPK];
        unsigned used = 0u;
        for (int k = 0; k < TOPK; k++) {
            float best = -INFINITY; int bi = 0;
            for (int i = 0; i < 16; i++)
                if (!((used >> i) & 1u) && logits[i] > best) { best = logits[i]; bi = i; }
            used |= (1u << bi); idx[k] = bi; val[k] = best;
        }
        float m = val[0];
        float g[TOPK], s = 0.f;
        #pragma unroll
        for (int k = 0; k < TOPK; k++) { g[k] = expf(val[k] - m); s += g[k]; }
        #pragma unroll
        for (int k = 0; k < TOPK; k++) {
            int ex = idx[k];
            int rank = atomicAdd(&g_cnt[ex], 1);
            int slot = ex * CAP + rank;
            s_slot[k]          = slot;
            g_slot[b * 4 + k]  = slot;
            g_gate[b * 4 + k]  = g[k] / s;
        }
    }
    __syncthreads();

    // pack x to bf16x2 once, scatter to 4 expert slots
    __shared__ uint32_t sxp[D_IN / 2];
    for (int i = t; i < D_IN / 2; i += 256)
        sxp[i] = packbf(sx[2 * i], sx[2 * i + 1]);
    __syncthreads();
    #pragma unroll
    for (int k = 0; k < TOPK; k++) {
        uint32_t* dst = g_xa + (size_t)s_slot[k] * (D_IN / 2);
        for (int i = t; i < D_IN / 2; i += 256) dst[i] = sxp[i];
    }
}

// ---------------- bf16 mma grouped GEMM ----------------
// A: [E*CAP][Ktot/2] u32 (bf16 pairs, k-contig). B: [E][Ktot/2][Ntot] u32 (bf16x2 per k-pair).
// C = act(A@B + bias): OUTBF -> bf16x2 u32 rows; else f32 rows.
template<bool RELU, bool OUTBF>
__global__ void __launch_bounds__(256, 2)
gemm_bf16(const uint32_t* __restrict__ A, const uint32_t* __restrict__ B,
          const float* __restrict__ bias, void* __restrict__ Cv,
          int Ktot, int Ntot) {
    extern __shared__ char smem[];
    const int e  = blockIdx.z;
    const int M  = g_cnt[e];
    const int m0 = blockIdx.y * BM;
    if (m0 >= M) return;
    const int n0 = blockIdx.x * BN;

    const uint32_t sbase = smem_u32(smem);
    const int tid = threadIdx.x;
    const int wid = tid >> 5, lane = tid & 31;
    const int wm = wid >> 2;          // 0..1
    const int wn = wid & 3;           // 0..3
    const int r  = lane >> 2;         // 0..7
    const int c  = lane & 3;          // 0..3

    const int Kw = Ktot / 2;
    const uint32_t* Abase = A + (size_t)(e * CAP + m0) * Kw;
    const uint32_t* Bbase = B + (size_t)e * Kw * Ntot + n0;
    const int KT = Ktot / BK;

    const int a_row = tid >> 1;              // 0..127
    const int a_ch  = (tid & 1) * 2;
    const int b_row = tid >> 4;              // 0..15
    const int b_ch  = (tid & 15) * 2;

    auto load_stage = [&](int kt) {
        uint32_t sa = sbase + (kt & 3) * STAGE_BYTES;
        uint32_t sb = sa + A_STAGE;
        const uint32_t* ga = Abase + kt * KPW;
        const uint32_t* gb = Bbase + (size_t)(kt * 16) * Ntot;
        cp16(sa + a_row * (A_STRIDE * 4) + a_ch * 16,       ga + (size_t)a_row * Kw + a_ch * 4);
        cp16(sa + a_row * (A_STRIDE * 4) + (a_ch + 1) * 16, ga + (size_t)a_row * Kw + (a_ch + 1) * 4);
        cp16(sb + b_row * (B_STRIDE * 4) + b_ch * 16,       gb + (size_t)b_row * Ntot + b_ch * 4);
        cp16(sb + b_row * (B_STRIDE * 4) + (b_ch + 1) * 16, gb + (size_t)b_row * Ntot + (b_ch + 1) * 4);
        asm volatile("cp.async.commit_group;" ::: "memory");
    };

    load_stage(0);
    load_stage(1);
    load_stage(2);

    float acc[4][4][4];
    #pragma unroll
    for (int i = 0; i < 4; i++)
        #pragma unroll
        for (int j = 0; j < 4; j++)
            #pragma unroll
            for (int k = 0; k < 4; k++) acc[i][j][k] = 0.f;

    // per-thread smem fragment bases (u32 addresses)
    const uint32_t a_fb = sbase + ((wm * 64 + r) * A_STRIDE + c) * 4;
    const uint32_t b_fb = sbase + A_STAGE + (c * B_STRIDE + wn * 32 + r) * 4;

    for (int kt = 0; kt < KT; kt++) {
        asm volatile("cp.async.wait_group 2;" ::: "memory");
        __syncthreads();
        if (kt + 3 < KT) load_stage(kt + 3);
        else asm volatile("cp.async.commit_group;" ::: "memory");

        uint32_t sa = a_fb + (kt & 3) * STAGE_BYTES;
        uint32_t sb = b_fb + (kt & 3) * STAGE_BYTES;
        #pragma unroll
        for (int ks = 0; ks < 2; ks++) {
            uint32_t af[4][4];
            #pragma unroll
            for (int mt = 0; mt < 4; mt++) {
                uint32_t base = sa + (mt * 16) * (A_STRIDE * 4) + ks * 32;
                asm volatile("ld.shared.b32 %0, [%1];"       : "=r"(af[mt][0]) : "r"(base));
                asm volatile("ld.shared.b32 %0, [%1];"       : "=r"(af[mt][1]) : "r"(base + 8 * A_STRIDE * 4));
                asm volatile("ld.shared.b32 %0, [%1];"       : "=r"(af[mt][2]) : "r"(base + 16));
                asm volatile("ld.shared.b32 %0, [%1];"       : "=r"(af[mt][3]) : "r"(base + 8 * A_STRIDE * 4 + 16));
            }
            uint32_t bf[4][2];
            #pragma unroll
            for (int nt = 0; nt < 4; nt++) {
                uint32_t base = sb + ks * (8 * B_STRIDE * 4) + nt * 32;
                asm volatile("ld.shared.b32 %0, [%1];" : "=r"(bf[nt][0]) : "r"(base));
                asm volatile("ld.shared.b32 %0, [%1];" : "=r"(bf[nt][1]) : "r"(base + 4 * B_STRIDE * 4));
            }
            #pragma unroll
            for (int mt = 0; mt < 4; mt++)
                #pragma unroll
                for (int nt = 0; nt < 4; nt++)
                    mma_bf16(acc[mt][nt], af[mt], bf[nt]);
        }
        __syncthreads();
    }
    asm volatile("cp.async.wait_group 0;" ::: "memory");

    // epilogue
    #pragma unroll
    for (int nt = 0; nt < 4; nt++) {
        int col = n0 + wn * 32 + nt * 8 + 2 * c;
        float bb0 = __ldg(bias + e * Ntot + col);
        float bb1 = __ldg(bias + e * Ntot + col + 1);
        #pragma unroll
        for (int mt = 0; mt < 4; mt++) {
            int row0 = wm * 64 + mt * 16 + r;
            float v0 = acc[mt][nt][0] + bb0;
            float v1 = acc[mt][nt][1] + bb1;
            float v2 = acc[mt][nt][2] + bb0;
            float v3 = acc[mt][nt][3] + bb1;
            if (RELU) {
                v0 = fmaxf(v0, 0.f); v1 = fmaxf(v1, 0.f);
                v2 = fmaxf(v2, 0.f); v3 = fmaxf(v3, 0.f);
            }
            if (OUTBF) {
                uint32_t* C = (uint32_t*)Cv;
                int cw = col >> 1;
                if (m0 + row0 < M)
                    C[(size_t)(e * CAP + m0 + row0) * (Ntot / 2) + cw] = packbf(v0, v1);
                if (m0 + row0 + 8 < M)
                    C[(size_t)(e * CAP + m0 + row0 + 8) * (Ntot / 2) + cw] = packbf(v2, v3);
            } else {
                float* C = (float*)Cv;
                if (m0 + row0 < M) {
                    float2 p = {v0, v1};
                    *(float2*)(C + (size_t)(e * CAP + m0 + row0) * Ntot + col) = p;
                }
                if (m0 + row0 + 8 < M) {
                    float2 p = {v2, v3};
                    *(float2*)(C + (size_t)(e * CAP + m0 + row0 + 8) * Ntot + col) = p;
                }
            }
        }
    }
}

// ---------------- combine ----------------
__global__ void combine_kernel(float* __restrict__ out) {
    int b = blockIdx.x;
    __shared__ float vals[TOPK][NHEAD];
    __shared__ float mx[TOPK][3], inv[TOPK][3];
    __shared__ int   slots[TOPK];
    __shared__ float gts[TOPK];
    int t = threadIdx.x;

    if (t < TOPK) { slots[t] = g_slot[b * 4 + t]; gts[t] = g_gate[b * 4 + t]; }
    __syncthreads();

    for (int i = t; i < TOPK * NHEAD; i += 256) {
        int k = i / NHEAD, cc = i % NHEAD;
        vals[k][cc] = g_hl[(size_t)slots[k] * NHEAD_PAD + cc];
    }
    __syncthreads();

    if (t < TOPK * 3) {
        int k = t / 3, grp = t % 3;
        int c0 = (grp == 0) ? 0 : (grp == 1 ? 36 : 72);
        int c1 = (grp == 0) ? 36 : (grp == 1 ? 72 : 204);
        float m = -INFINITY;
        for (int cc = c0; cc < c1; cc++) m = fmaxf(m, vals[k][cc]);
        float s = 0.f;
        for (int cc = c0; cc < c1; cc++) s += expf(vals[k][cc] - m);
        mx[k][grp]  = m;
        inv[k][grp] = 1.f / s;
    }
    __syncthreads();

    if (t < NHEAD) {
        int grp = (t < 36) ? 0 : ((t < 72) ? 1 : 2);
        float s = 0.f;
        #pragma unroll
        for (int k = 0; k < TOPK; k++)
            s += gts[k] * expf(vals[k][t] - mx[k][grp]) * inv[k][grp];
        float res = logf((s == 0.f) ? EPS_F : s);
        if (t < 36)       out[b * 36 + t] = res;
        else if (t < 72)  out[B_TOK * 36 + b * 36 + (t - 36)] = res;
        else              out[B_TOK * 72 + b * 132 + (t - 72)] = res;
    }
}

// ---------------- launch ----------------
extern "C" void kernel_launch(void* const* d_in, const int* in_sizes, int n_in,
                              void* d_out, int out_size) {
    const float* sf  = (const float*)d_in[0];
    const float* of  = (const float*)d_in[1];
    const float* ppf = (const float*)d_in[2];
    const float* pvf = (const float*)d_in[3];
    const float* wg  = (const float*)d_in[4];
    const float* wn  = (const float*)d_in[5];
    const float* W1  = (const float*)d_in[6];
    const float* b1  = (const float*)d_in[7];
    const float* W2  = (const float*)d_in[8];
    const float* b2  = (const float*)d_in[9];
    const float* Ws  = (const float*)d_in[10];
    const float* bs  = (const float*)d_in[11];
    const float* Wo  = (const float*)d_in[12];
    const float* bo  = (const float*)d_in[13];
    const float* Wp  = (const float*)d_in[14];
    const float* bp  = (const float*)d_in[15];
    const float* noise = (const float*)d_in[16];
    float* out = (float*)d_out;

    static uint32_t* p_xa  = nullptr;
    static uint32_t* p_h1  = nullptr;
    static uint32_t* p_h2  = nullptr;
    static float*    p_hl  = nullptr;
    static uint32_t* p_w1b = nullptr;
    static uint32_t* p_w2b = nullptr;
    static uint32_t* p_whb = nullptr;
    static float*    p_bh  = nullptr;
    if (!p_xa) {
        cudaGetSymbolAddress((void**)&p_xa,  g_xa);
        cudaGetSymbolAddress((void**)&p_h1,  g_h1);
        cudaGetSymbolAddress((void**)&p_h2,  g_h2);
        cudaGetSymbolAddress((void**)&p_hl,  g_hl);
        cudaGetSymbolAddress((void**)&p_w1b, g_w1b);
        cudaGetSymbolAddress((void**)&p_w2b, g_w2b);
        cudaGetSymbolAddress((void**)&p_whb, g_whb);
        cudaGetSymbolAddress((void**)&p_bh,  g_bh);
        cudaFuncSetAttribute(gemm_bf16<true, true>,
                             cudaFuncAttributeMaxDynamicSharedMemorySize, SMEM_GEMM);
        cudaFuncSetAttribute(gemm_bf16<false, false>,
                             cudaFuncAttributeMaxDynamicSharedMemorySize, SMEM_GEMM);
    }

    init_kernel<<<1, 32>>>();
    gating_kernel<<<B_TOK, 256>>>(sf, of, ppf, pvf, wg, wn, noise);
    conv_w<<<(int)(((size_t)E_EXP * (D_IN / 2) * H_DIM) / 256), 256>>>(W1, p_w1b, D_IN / 2, H_DIM);
    conv_w<<<(int)(((size_t)E_EXP * (H_DIM / 2) * H_DIM) / 256), 256>>>(W2, p_w2b, H_DIM / 2, H_DIM);
    pack_heads<<<(int)(((size_t)E_EXP * (H_DIM / 2) * NHEAD_PAD) / 256), 256>>>(Ws, bs, Wo, bo, Wp, bp);

    // L1: [cnt_e,1536] @ W1[e] -> relu -> h1 (bf16)
    gemm_bf16<true, true><<<dim3(H_DIM / BN, CAP / BM, E_EXP), 256, SMEM_GEMM>>>(
        p_xa, p_w1b, b1, p_h1, D_IN, H_DIM);
    // L2: [cnt_e,1024] @ W2[e] -> relu -> h2 (bf16)
    gemm_bf16<true, true><<<dim3(H_DIM / BN, CAP / BM, E_EXP), 256, SMEM_GEMM>>>(
        p_h1, p_w2b, b2, p_h2, H_DIM, H_DIM);
    // heads: [cnt_e,1024] @ Wh[e] (N=256 packed) -> f32 logits
    gemm_bf16<false, false><<<dim3(NHEAD_PAD / BN, CAP / BM, E_EXP), 256, SMEM_GEMM>>>(
        p_h2, p_whb, p_bh, p_hl, H_DIM, NHEAD_PAD);

    combine_kernel<<<B_TOK, 256>>>(out);
}